// round 6
// baseline (speedup 1.0000x reference)
#include <cuda_runtime.h>
#include <math.h>

// Problem constants
#define NP     2048     // particles
#define NR     128      // rays
#define NS     256      // ray steps
#define MAPW   1024
#define MAPH   1024
#define ND     256      // sensor table dim
#define OCC_THRESH 0.97f

// Map window that can ever be sampled (particles ~N(512,20^2) +-3.6 sigma,
// rays reach <=256.5):  y in [176, 848), x words 5..26  (x in [160, 864)).
#define WINY0   176
#define WROWS   672
#define WINXW0  5            // first x bitmap word
#define WWORDS  22           // x words per row (covers x in [160,864))
#define WPAD    23           // padded row stride, odd -> conflict-free banks
#define WIN_U32 (WROWS * WPAD)

#define PPB  14              // particles per block
#define TPB  (PPB * 64)      // 896 threads, 2 warps per particle
#define GRID ((NP + PPB - 1) / PPB)   // 147 -> one wave on 148 SMs

// Scratch (no cudaMalloc allowed)
__device__ float    g_pred[NP * 3];     // predicted particles
__device__ float    g_trig[NP * 2];     // sin(th), cos(th)
__device__ float    g_logl[NP];         // per-particle log likelihood
__device__ float    g_logits[NP];       // log_weights + log_l
__device__ __align__(16) unsigned g_bitmap[MAPW * MAPH / 32];  // 128 KB occupancy bits
__device__ int      g_perm[NR];         // rays sorted by angle

// ---------------------------------------------------------------------------
// Setup: blocks 0..1023 build the occupancy bitmap (float4 loads, 4 cells per
// thread, 8-lane OR-reduce packing); block 1024 rank-sorts the ray angles.
// ---------------------------------------------------------------------------
__global__ __launch_bounds__(256) void kernSetup(
    const float* __restrict__ map_grid,
    const float* __restrict__ obs_angles)
{
    if (blockIdx.x < 1024) {
        const int t = blockIdx.x * 256 + threadIdx.x;     // 0 .. 262143
        const float4 v = __ldg(&((const float4*)map_grid)[t]);
        unsigned b = (v.x > OCC_THRESH ? 1u : 0u)
                   | (v.y > OCC_THRESH ? 2u : 0u)
                   | (v.z > OCC_THRESH ? 4u : 0u)
                   | (v.w > OCC_THRESH ? 8u : 0u);
        const int lane = threadIdx.x & 31;
        const int grp  = lane >> 3;                        // 8-lane group
        const unsigned gmask = 0xFFu << (grp * 8);
        unsigned word = __reduce_or_sync(gmask, b << ((lane & 7) * 4));
        if ((lane & 7) == 0) g_bitmap[t >> 3] = word;
    } else {
        __shared__ float s_a[NR];
        const int i = threadIdx.x;
        if (i < NR) s_a[i] = obs_angles[i];
        __syncthreads();
        if (i < NR) {
            const float a = s_a[i];
            int rank = 0;
            #pragma unroll 8
            for (int j = 0; j < NR; j++) {
                float b = s_a[j];
                rank += (b < a) || (b == a && j < i);
            }
            g_perm[rank] = i;
        }
    }
}

// ---------------------------------------------------------------------------
// Kernel A: 14 particles/block, 2 warps/particle; each warp serially marches
// its 64 (angle-sorted) rays, 32 steps per iteration with ballot first-hit.
// Bitmap window cached in padded smem.  Per-ray values stored by ORIGINAL
// ray index; reduction reproduces the exact R1 tree (bit-identical).
// ---------------------------------------------------------------------------
__global__ __launch_bounds__(TPB, 2) void kernA(
    const float* __restrict__ particles,
    const float* __restrict__ log_weights,
    const float* __restrict__ obs_angles,
    const float* __restrict__ obs_dists,
    const float* __restrict__ sensor_table,
    const float* __restrict__ twist,
    const float* __restrict__ motion_noise)
{
    extern __shared__ unsigned smw[];
    unsigned* sm_bm  = smw;                               // WROWS*WPAD u32
    float*    s_val  = (float*)(smw + WIN_U32);           // PPB*128 floats
    float*    s_part = s_val + PPB * 128;                 // PPB*4 floats

    const int tid = threadIdx.x;

    // ---- load bitmap window into padded smem rows ----
    for (int i = tid; i < WROWS * WWORDS; i += TPB) {
        int row = i / WWORDS;
        int j   = i - row * WWORDS;
        sm_bm[row * WPAD + j] = __ldg(&g_bitmap[(row + WINY0) * 32 + WINXW0 + j]);
    }

    const int pi   = tid >> 6;        // particle within block (0..13)
    const int q    = tid & 63;        // thread within particle
    const int h    = q >> 5;          // warp half (0 or 1): handles slots h*64..h*64+63
    const int lane = tid & 31;
    const int p    = blockIdx.x * PPB + pi;
    const bool active = (p < NP);     // uniform per warp

    float x = 0.f, y = 0.f;
    float cA = 0.f, sA = 0.f, cB = 0.f, sB = 0.f;
    int rayA = 0, rayB = 0;
    bool inwA = false, inwB = false;

    if (active) {
        const int slotA = h * 64 + lane;        // sorted-rank slots this thread owns
        const int slotB = h * 64 + 32 + lane;
        rayA = g_perm[slotA];
        rayB = g_perm[slotB];

        // Motion update (mul then add, no FMA contraction)
        x        = __fadd_rn(__fadd_rn(particles[p*3+0], twist[0]),
                             __fmul_rn(motion_noise[p*3+0], 0.5f));
        y        = __fadd_rn(__fadd_rn(particles[p*3+1], twist[1]),
                             __fmul_rn(motion_noise[p*3+1], 0.5f));
        float th = __fadd_rn(__fadd_rn(particles[p*3+2], twist[2]),
                             __fmul_rn(motion_noise[p*3+2], 0.02f));
        if (q < 3) g_pred[p*3 + q] = (q == 0) ? x : ((q == 1) ? y : th);
        if (q == 3) g_trig[p*2 + 0] = sinf(th);
        if (q == 4) g_trig[p*2 + 1] = cosf(th);

        float angA = __fadd_rn(th, obs_angles[rayA]);
        float angB = __fadd_rn(th, obs_angles[rayB]);
        cA = cosf(angA); sA = sinf(angA);
        cB = cosf(angB); sB = sinf(angB);

        // In-window tests (segment t in [1,256] is convex)
        {
            float ex0 = __fadd_rn(x, cA), ex1 = __fadd_rn(x, __fmul_rn(256.f, cA));
            float ey0 = __fadd_rn(y, sA), ey1 = __fadd_rn(y, __fmul_rn(256.f, sA));
            inwA = (fminf(ex0, ex1) >= 162.f) && (fmaxf(ex0, ex1) < 862.f) &&
                   (fminf(ey0, ey1) >= (float)(WINY0 + 2)) &&
                   (fmaxf(ey0, ey1) < (float)(WINY0 + WROWS - 2));
            ex0 = __fadd_rn(x, cB); ex1 = __fadd_rn(x, __fmul_rn(256.f, cB));
            ey0 = __fadd_rn(y, sB); ey1 = __fadd_rn(y, __fmul_rn(256.f, sB));
            inwB = (fminf(ex0, ex1) >= 162.f) && (fmaxf(ex0, ex1) < 862.f) &&
                   (fminf(ey0, ey1) >= (float)(WINY0 + 2)) &&
                   (fmaxf(ey0, ey1) < (float)(WINY0 + WROWS - 2));
        }
    }

    __syncthreads();   // smem bitmap ready

    int ebinA = 255, ebinB = 255;   // no-hit: clip(int(256),0,255)=255
    if (active) {
        const unsigned maskA = __ballot_sync(0xffffffffu, inwA);
        const unsigned maskB = __ballot_sync(0xffffffffu, inwB);
        const float lanef = (float)(lane + 1);

        #pragma unroll 1
        for (int rr = 0; rr < 64; rr++) {
            const float cc = (rr < 32) ? cA : cB;
            const float ss = (rr < 32) ? sA : sB;
            const float rc = __shfl_sync(0xffffffffu, cc, rr & 31);
            const float rs = __shfl_sync(0xffffffffu, ss, rr & 31);
            const unsigned inw = (rr < 32) ? ((maskA >> rr) & 1u)
                                           : ((maskB >> (rr - 32)) & 1u);
            int ebin = 255;
            if (inw) {
                // Fast path: padded smem window, no clamping needed.
                float tf = lanef;
                #pragma unroll 1
                for (int it = 0; it < 8; it++) {
                    float px = __fadd_rn(x, __fmul_rn(tf, rc));
                    float py = __fadd_rn(y, __fmul_rn(tf, rs));
                    int ix = __float2int_rz(px);
                    int iy = __float2int_rz(py);
                    unsigned w = sm_bm[(iy - WINY0) * WPAD + ((ix >> 5) - WINXW0)];
                    unsigned m = __ballot_sync(0xffffffffu, (w >> (ix & 31)) & 1u);
                    if (m) { ebin = min(it * 32 + __ffs(m), 255); break; }
                    tf = __fadd_rn(tf, 32.0f);
                }
            } else {
                // Fallback: global bitmap, full clamping (outliers only).
                float tf = lanef;
                #pragma unroll 1
                for (int it = 0; it < 8; it++) {
                    float px = __fadd_rn(x, __fmul_rn(tf, rc));
                    float py = __fadd_rn(y, __fmul_rn(tf, rs));
                    int ix = min(max(__float2int_rz(px), 0), MAPW - 1);
                    int iy = min(max(__float2int_rz(py), 0), MAPH - 1);
                    unsigned w = __ldg(&g_bitmap[(iy << 5) + (ix >> 5)]);
                    unsigned m = __ballot_sync(0xffffffffu, (w >> (ix & 31)) & 1u);
                    if (m) { ebin = min(it * 32 + __ffs(m), 255); break; }
                    tf = __fadd_rn(tf, 32.0f);
                }
            }
            if (lane == (rr & 31)) {
                if (rr < 32) ebinA = ebin; else ebinB = ebin;
            }
        }

        // bin_w = 1.0 exactly: o_bin = clip(int(obs_dist),0,255)
        int obA = min(max(__float2int_rz(obs_dists[rayA]), 0), ND - 1);
        int obB = min(max(__float2int_rz(obs_dists[rayB]), 0), ND - 1);
        s_val[pi * 128 + rayA] = __ldg(&sensor_table[ebinA * ND + obA]);
        s_val[pi * 128 + rayB] = __ldg(&sensor_table[ebinB * ND + obB]);
    }
    __syncthreads();

    // Reduce in the exact R1 order: group g holds rays g*32+lane in lane
    // `lane`; warp h computes groups 2h and 2h+1 with identical shfl trees.
    if (active) {
        #pragma unroll
        for (int k = 0; k < 2; k++) {
            const int g = 2 * h + k;
            float v = s_val[pi * 128 + g * 32 + lane];
            #pragma unroll
            for (int o = 16; o > 0; o >>= 1)
                v += __shfl_down_sync(0xffffffffu, v, o);
            if (lane == 0) s_part[pi * 4 + g] = v;
        }
    }
    __syncthreads();
    if (active && q == 0) {
        float ll = ((s_part[pi*4+0] + s_part[pi*4+1]) + s_part[pi*4+2]) + s_part[pi*4+3];
        g_logl[p] = ll;
        g_logits[p] = __fadd_rn(log_weights[p], __fmul_rn(1.0f, ll));
    }
}

// ---------------------------------------------------------------------------
// Kernel B: single block, 1024 threads.  EXACT R1 arithmetic/order for max,
// softmax sums, estimates; ping-pong Kogge-Stone scan (same operands/order,
// 1 barrier per round); in-block resample tail (R1 arithmetic).
// ---------------------------------------------------------------------------
__device__ __forceinline__ float blockReduceSum(float v, float* s_red) {
    #pragma unroll
    for (int o = 16; o > 0; o >>= 1)
        v += __shfl_down_sync(0xffffffffu, v, o);
    int w = threadIdx.x >> 5, l = threadIdx.x & 31;
    if (l == 0) s_red[w] = v;
    __syncthreads();
    if (w == 0) {
        v = s_red[l];
        #pragma unroll
        for (int o = 16; o > 0; o >>= 1)
            v += __shfl_down_sync(0xffffffffu, v, o);
        if (l == 0) s_red[0] = v;
    }
    __syncthreads();
    float res = s_red[0];
    __syncthreads();
    return res;
}

__device__ __forceinline__ float blockReduceMax(float v, float* s_red) {
    #pragma unroll
    for (int o = 16; o > 0; o >>= 1)
        v = fmaxf(v, __shfl_down_sync(0xffffffffu, v, o));
    int w = threadIdx.x >> 5, l = threadIdx.x & 31;
    if (l == 0) s_red[w] = v;
    __syncthreads();
    if (w == 0) {
        v = s_red[l];
        #pragma unroll
        for (int o = 16; o > 0; o >>= 1)
            v = fmaxf(v, __shfl_down_sync(0xffffffffu, v, o));
        if (l == 0) s_red[0] = v;
    }
    __syncthreads();
    float res = s_red[0];
    __syncthreads();
    return res;
}

__global__ __launch_bounds__(1024) void kernB(
    const float* __restrict__ noise_after,
    const float* __restrict__ resample_u,
    float* __restrict__ out)
{
    __shared__ float s_buf0[NP];
    __shared__ float s_buf1[NP];
    __shared__ float s_red[32];

    const int tid = threadIdx.x;
    const int i0 = tid, i1 = tid + 1024;

    // --- max of logits ---
    float l0 = g_logits[i0];
    float l1 = g_logits[i1];
    float mx = blockReduceMax(fmaxf(l0, l1), s_red);
    float mx10 = __fmul_rn(mx, 10.0f);

    // --- exp terms + fused weighted partial sums ---
    float S10 = 0.f, Sx = 0.f, Sy = 0.f, Ssin = 0.f, Scos = 0.f;
    float S1 = 0.f, Sconf = 0.f;
    #pragma unroll
    for (int k = 0; k < 2; k++) {
        int i = (k == 0) ? i0 : i1;
        float l = (k == 0) ? l0 : l1;
        float e10 = expf(__fsub_rn(__fmul_rn(l, 10.0f), mx10));
        float e1  = expf(__fsub_rn(l, mx));
        float px = g_pred[i*3+0];
        float py = g_pred[i*3+1];
        S10  += e10;
        Sx   += e10 * px;
        Sy   += e10 * py;
        Ssin += e10 * g_trig[i*2+0];   // == e10 * sinf(pth), same bits
        Scos += e10 * g_trig[i*2+1];   // == e10 * cosf(pth), same bits
        S1   += e1;
        Sconf += e1 * g_logl[i];
        s_buf0[i] = e1;
    }
    S10   = blockReduceSum(S10, s_red);
    Sx    = blockReduceSum(Sx, s_red);
    Sy    = blockReduceSum(Sy, s_red);
    Ssin  = blockReduceSum(Ssin, s_red);
    Scos  = blockReduceSum(Scos, s_red);
    S1    = blockReduceSum(S1, s_red);
    Sconf = blockReduceSum(Sconf, s_red);

    // --- normalize weights ---
    s_buf0[i0] = s_buf0[i0] / S1;
    s_buf0[i1] = s_buf0[i1] / S1;
    __syncthreads();

    // --- Kogge-Stone inclusive scan, ping-pong buffers.
    //     dst[i] = src[i] + src[i-stride]: identical operands & order to the
    //     in-place version, 1 barrier per round.  11 rounds -> ends in buf1.
    float* src = s_buf0;
    float* dst = s_buf1;
    for (int stride = 1; stride < NP; stride <<= 1) {
        float a0 = src[i0] + ((i0 >= stride) ? src[i0 - stride] : 0.f);
        float a1 = src[i1] + ((i1 >= stride) ? src[i1 - stride] : 0.f);
        // note: when i < stride, dst[i] = src[i] (+0 skipped to keep bits)
        dst[i0] = (i0 >= stride) ? a0 : src[i0];
        dst[i1] = (i1 >= stride) ? a1 : src[i1];
        __syncthreads();
        float* tmp = src; src = dst; dst = tmp;
    }
    float* s_cum = src;   // final scan result

    // --- systematic resampling: idx = searchsorted(cum, (i+u)/P), left ----
    const float u = resample_u[0];
    #pragma unroll
    for (int k = 0; k < 2; k++) {
        int i = (k == 0) ? i0 : i1;
        float pos = __fdiv_rn(__fadd_rn((float)i, u), (float)NP);
        int lo = 0, hi = NP;
        while (lo < hi) {
            int mid = (lo + hi) >> 1;
            if (s_cum[mid] < pos) lo = mid + 1;
            else hi = mid;
        }
        int idx = min(lo, NP - 1);
        out[3 + i*3 + 0] = __fadd_rn(g_pred[idx*3+0], __fmul_rn(noise_after[i*3+0], 0.2f));
        out[3 + i*3 + 1] = __fadd_rn(g_pred[idx*3+1], __fmul_rn(noise_after[i*3+1], 0.2f));
        out[3 + i*3 + 2] = __fadd_rn(g_pred[idx*3+2], __fmul_rn(noise_after[i*3+2], 0.01f));
    }

    if (tid == 0) {
        out[0] = Sx / S10;
        out[1] = Sy / S10;
        out[2] = atan2f(Ssin / S10, Scos / S10);
        out[3 + NP * 3] = Sconf / S1;   // confidence, last element
    }
}

// ---------------------------------------------------------------------------
// Launch
// ---------------------------------------------------------------------------
extern "C" void kernel_launch(void* const* d_in, const int* in_sizes, int n_in,
                              void* d_out, int out_size)
{
    const float* particles    = (const float*)d_in[0];
    const float* log_weights  = (const float*)d_in[1];
    const float* obs_angles   = (const float*)d_in[2];
    const float* obs_dists    = (const float*)d_in[3];
    const float* map_grid     = (const float*)d_in[4];
    const float* sensor_table = (const float*)d_in[5];
    const float* twist        = (const float*)d_in[6];
    const float* motion_noise = (const float*)d_in[7];
    const float* resample_u   = (const float*)d_in[8];
    const float* noise_after  = (const float*)d_in[9];
    float* out = (float*)d_out;

    // Dynamic smem: padded bitmap window + per-ray values + partials
    const int smemA = WIN_U32 * 4 + PPB * 128 * 4 + PPB * 4 * 4;   // ~69 KB
    cudaFuncSetAttribute(kernA, cudaFuncAttributeMaxDynamicSharedMemorySize, smemA);

    kernSetup<<<1025, 256>>>(map_grid, obs_angles);
    kernA<<<GRID, TPB, smemA>>>(particles, log_weights, obs_angles, obs_dists,
                                sensor_table, twist, motion_noise);
    kernB<<<1, 1024>>>(noise_after, resample_u, out);
}

// round 7
// speedup vs baseline: 1.0925x; 1.0925x over previous
#include <cuda_runtime.h>
#include <math.h>

// Problem constants
#define NP     2048     // particles
#define NR     128      // rays
#define NS     256      // ray steps
#define MAPW   1024
#define MAPH   1024
#define ND     256      // sensor table dim
#define OCC_THRESH 0.97f

// Map window that can ever be sampled (particles ~N(512,20^2) +-3.6 sigma,
// rays reach <=256.5):  y in [176, 848), x words 5..26  (x in [160, 864)).
#define WINY0   176
#define WROWS   672
#define WINXW0  5            // first x bitmap word
#define WWORDS  22           // x words per row (covers x in [160,864))
#define WPAD    23           // padded row stride, odd -> conflict-free banks
#define WIN_U32 (WROWS * WPAD)

#define PPB 7                // particles per block
#define TPB (PPB * 128)      // 896 threads
#define GRID ((NP + PPB - 1) / PPB)   // 293 -> 2 blocks/SM, 56 warps/SM

// Scratch (no cudaMalloc allowed)
__device__ float    g_pred[NP * 3];     // predicted particles
__device__ float    g_trig[NP * 2];     // sin(th), cos(th)
__device__ float    g_logl[NP];         // per-particle log likelihood
__device__ float    g_logits[NP];       // log_weights + log_l
__device__ __align__(16) unsigned g_bitmap[MAPW * MAPH / 32];  // 128 KB occupancy bits
__device__ int      g_perm[NR];         // rays sorted by angle

// ---------------------------------------------------------------------------
// Setup: blocks 0..1023 build the occupancy bitmap (float4 loads, 4 cells per
// thread, 8-lane OR-reduce packing); block 1024 rank-sorts the ray angles.
// ---------------------------------------------------------------------------
__global__ __launch_bounds__(256) void kernSetup(
    const float* __restrict__ map_grid,
    const float* __restrict__ obs_angles)
{
    if (blockIdx.x < 1024) {
        const int t = blockIdx.x * 256 + threadIdx.x;     // 0 .. 262143
        const float4 v = __ldg(&((const float4*)map_grid)[t]);
        unsigned b = (v.x > OCC_THRESH ? 1u : 0u)
                   | (v.y > OCC_THRESH ? 2u : 0u)
                   | (v.z > OCC_THRESH ? 4u : 0u)
                   | (v.w > OCC_THRESH ? 8u : 0u);
        const int lane = threadIdx.x & 31;
        const int grp  = lane >> 3;                        // 8-lane group
        const unsigned gmask = 0xFFu << (grp * 8);
        unsigned word = __reduce_or_sync(gmask, b << ((lane & 7) * 4));
        if ((lane & 7) == 0) g_bitmap[t >> 3] = word;
    } else {
        __shared__ float s_a[NR];
        const int i = threadIdx.x;
        if (i < NR) s_a[i] = obs_angles[i];
        __syncthreads();
        if (i < NR) {
            const float a = s_a[i];
            int rank = 0;
            #pragma unroll 8
            for (int j = 0; j < NR; j++) {
                float b = s_a[j];
                rank += (b < a) || (b == a && j < i);
            }
            g_perm[rank] = i;
        }
    }
}

// ---------------------------------------------------------------------------
// Kernel A (R5 layout): 7 particles/block, 128 threads/particle; each warp
// serially processes its 32 (angle-sorted) rays, 32 steps/iteration with
// ballot first-hit.  Bitmap window cached in padded smem.  Per-ray values
// stored by ORIGINAL ray index; reduction in exact R1 order.
// ---------------------------------------------------------------------------
__global__ __launch_bounds__(TPB, 2) void kernA(
    const float* __restrict__ particles,
    const float* __restrict__ log_weights,
    const float* __restrict__ obs_angles,
    const float* __restrict__ obs_dists,
    const float* __restrict__ sensor_table,
    const float* __restrict__ twist,
    const float* __restrict__ motion_noise)
{
    extern __shared__ unsigned smw[];
    unsigned* sm_bm  = smw;                               // WROWS*WPAD u32
    float*    s_val  = (float*)(smw + WIN_U32);           // PPB*128 floats
    float*    s_part = s_val + PPB * 128;                 // PPB*4 floats

    const int tid = threadIdx.x;

    // ---- load bitmap window into padded smem rows ----
    for (int i = tid; i < WROWS * WWORDS; i += TPB) {
        int row = i / WWORDS;
        int j   = i - row * WWORDS;
        sm_bm[row * WPAD + j] = __ldg(&g_bitmap[(row + WINY0) * 32 + WINXW0 + j]);
    }

    const int pi   = tid >> 7;        // particle within block
    const int r    = tid & 127;       // sorted-rank ray slot
    const int lane = tid & 31;
    const int p    = blockIdx.x * PPB + pi;
    const bool active = (p < NP);     // uniform per warp

    float x = 0.f, y = 0.f, th = 0.f, c = 0.f, s = 0.f;
    int ray = 0;
    bool my_inw = false;
    if (active) {
        ray = g_perm[r];
        // Motion update (mul then add, no FMA contraction)
        x  = __fadd_rn(__fadd_rn(particles[p*3+0], twist[0]),
                       __fmul_rn(motion_noise[p*3+0], 0.5f));
        y  = __fadd_rn(__fadd_rn(particles[p*3+1], twist[1]),
                       __fmul_rn(motion_noise[p*3+1], 0.5f));
        th = __fadd_rn(__fadd_rn(particles[p*3+2], twist[2]),
                       __fmul_rn(motion_noise[p*3+2], 0.02f));
        if (r < 3) g_pred[p*3 + r] = (r == 0) ? x : ((r == 1) ? y : th);
        if (r == 3) g_trig[p*2 + 0] = sinf(th);
        if (r == 4) g_trig[p*2 + 1] = cosf(th);

        const float ang = __fadd_rn(th, obs_angles[ray]);
        c = cosf(ang);
        s = sinf(ang);

        // In-window test for this ray's whole segment (t in [1,256], convex)
        float ex0 = __fadd_rn(x, c), ex1 = __fadd_rn(x, __fmul_rn(256.f, c));
        float ey0 = __fadd_rn(y, s), ey1 = __fadd_rn(y, __fmul_rn(256.f, s));
        float xmn = fminf(ex0, ex1), xmx = fmaxf(ex0, ex1);
        float ymn = fminf(ey0, ey1), ymx = fmaxf(ey0, ey1);
        my_inw = (xmn >= 162.f) && (xmx < 862.f) &&
                 (ymn >= (float)(WINY0 + 2)) && (ymx < (float)(WINY0 + WROWS - 2));
    }

    __syncthreads();   // smem bitmap ready

    int my_ebin = 255;   // no-hit: dist=256 -> clip(int(256),0,255)=255
    if (active) {
        const unsigned inw_mask = __ballot_sync(0xffffffffu, my_inw);
        const float lanef = (float)(lane + 1);

        #pragma unroll 1
        for (int rr = 0; rr < 32; rr++) {
            const float rc = __shfl_sync(0xffffffffu, c, rr);
            const float rs = __shfl_sync(0xffffffffu, s, rr);
            int ebin = 255;
            if ((inw_mask >> rr) & 1u) {
                // Fast path: padded smem window, no clamping needed.
                float tf = lanef;
                #pragma unroll 1
                for (int it = 0; it < 8; it++) {
                    float px = __fadd_rn(x, __fmul_rn(tf, rc));
                    float py = __fadd_rn(y, __fmul_rn(tf, rs));
                    int ix = __float2int_rz(px);
                    int iy = __float2int_rz(py);
                    unsigned w = sm_bm[(iy - WINY0) * WPAD + ((ix >> 5) - WINXW0)];
                    unsigned m = __ballot_sync(0xffffffffu, (w >> (ix & 31)) & 1u);
                    if (m) { ebin = min(it * 32 + __ffs(m), 255); break; }
                    tf = __fadd_rn(tf, 32.0f);
                }
            } else {
                // Fallback: global bitmap, full clamping (outliers only).
                float tf = lanef;
                #pragma unroll 1
                for (int it = 0; it < 8; it++) {
                    float px = __fadd_rn(x, __fmul_rn(tf, rc));
                    float py = __fadd_rn(y, __fmul_rn(tf, rs));
                    int ix = min(max(__float2int_rz(px), 0), MAPW - 1);
                    int iy = min(max(__float2int_rz(py), 0), MAPH - 1);
                    unsigned w = __ldg(&g_bitmap[(iy << 5) + (ix >> 5)]);
                    unsigned m = __ballot_sync(0xffffffffu, (w >> (ix & 31)) & 1u);
                    if (m) { ebin = min(it * 32 + __ffs(m), 255); break; }
                    tf = __fadd_rn(tf, 32.0f);
                }
            }
            my_ebin = (lane == rr) ? ebin : my_ebin;
        }

        // bin_w = 1.0 exactly: o_bin = clip(int(obs_dist),0,255)
        int ob = min(max(__float2int_rz(obs_dists[ray]), 0), ND - 1);
        float val = __ldg(&sensor_table[my_ebin * ND + ob]);
        s_val[pi * 128 + ray] = val;          // store by ORIGINAL ray index
    }
    __syncthreads();

    // Reduce in the exact round-1 order: thread slot r <- ray r.
    if (active) {
        float v = s_val[pi * 128 + r];
        #pragma unroll
        for (int o = 16; o > 0; o >>= 1)
            v += __shfl_down_sync(0xffffffffu, v, o);
        if ((r & 31) == 0) s_part[pi * 4 + (r >> 5)] = v;
    }
    __syncthreads();
    if (active && r == 0) {
        float ll = ((s_part[pi*4+0] + s_part[pi*4+1]) + s_part[pi*4+2]) + s_part[pi*4+3];
        g_logl[p] = ll;
        g_logits[p] = __fadd_rn(log_weights[p], __fmul_rn(1.0f, ll));
    }
}

// ---------------------------------------------------------------------------
// Kernel B: single block, 1024 threads.  Max + 7 FUSED block reductions
// (each value keeps its own exact R1 shfl_down tree; only barriers between
// values removed), ping-pong Kogge-Stone scan, in-block resample tail.
// ---------------------------------------------------------------------------
__global__ __launch_bounds__(1024) void kernB(
    const float* __restrict__ noise_after,
    const float* __restrict__ resample_u,
    float* __restrict__ out)
{
    __shared__ float s_buf0[NP];
    __shared__ float s_buf1[NP];
    __shared__ float s_red[7 * 32];
    __shared__ float s_tot[8];

    const int tid  = threadIdx.x;
    const int lane = tid & 31;
    const int wrp  = tid >> 5;
    const int i0 = tid, i1 = tid + 1024;

    // --- max of logits (shfl_down tree, same as R1 blockReduceMax) ---
    float l0 = g_logits[i0];
    float l1 = g_logits[i1];
    {
        float v = fmaxf(l0, l1);
        #pragma unroll
        for (int o = 16; o > 0; o >>= 1)
            v = fmaxf(v, __shfl_down_sync(0xffffffffu, v, o));
        if (lane == 0) s_red[wrp] = v;
        __syncthreads();
        if (wrp == 0) {
            float m2 = s_red[lane];
            #pragma unroll
            for (int o = 16; o > 0; o >>= 1)
                m2 = fmaxf(m2, __shfl_down_sync(0xffffffffu, m2, o));
            if (lane == 0) s_tot[7] = m2;
        }
        __syncthreads();
    }
    const float mx   = s_tot[7];
    const float mx10 = __fmul_rn(mx, 10.0f);

    // --- exp terms + 7 fused weighted partial sums ---
    float acc[7] = {0.f, 0.f, 0.f, 0.f, 0.f, 0.f, 0.f};
    #pragma unroll
    for (int k = 0; k < 2; k++) {
        int i = (k == 0) ? i0 : i1;
        float l = (k == 0) ? l0 : l1;
        float e10 = expf(__fsub_rn(__fmul_rn(l, 10.0f), mx10));
        float e1  = expf(__fsub_rn(l, mx));
        float px = g_pred[i*3+0];
        float py = g_pred[i*3+1];
        acc[0] += e10;                  // S10
        acc[1] += e10 * px;             // Sx
        acc[2] += e10 * py;             // Sy
        acc[3] += e10 * g_trig[i*2+0];  // Ssin (same bits as e10*sinf(th))
        acc[4] += e10 * g_trig[i*2+1];  // Scos
        acc[5] += e1;                   // S1
        acc[6] += e1 * g_logl[i];       // Sconf
        s_buf0[i] = e1;
    }
    // Fused reductions: per-value trees identical to sequential blockReduceSum
    #pragma unroll
    for (int q = 0; q < 7; q++) {
        float v = acc[q];
        #pragma unroll
        for (int o = 16; o > 0; o >>= 1)
            v += __shfl_down_sync(0xffffffffu, v, o);
        if (lane == 0) s_red[q * 32 + wrp] = v;
    }
    __syncthreads();
    if (wrp == 0) {
        #pragma unroll
        for (int q = 0; q < 7; q++) {
            float v = s_red[q * 32 + lane];
            #pragma unroll
            for (int o = 16; o > 0; o >>= 1)
                v += __shfl_down_sync(0xffffffffu, v, o);
            if (lane == 0) s_tot[q] = v;
        }
    }
    __syncthreads();
    const float S1 = s_tot[5];

    // --- normalize weights ---
    s_buf0[i0] = s_buf0[i0] / S1;
    s_buf0[i1] = s_buf0[i1] / S1;
    __syncthreads();

    // --- Kogge-Stone inclusive scan, ping-pong (bit-exact, 1 barrier/round) ---
    float* src = s_buf0;
    float* dst = s_buf1;
    for (int stride = 1; stride < NP; stride <<= 1) {
        float a0 = src[i0] + ((i0 >= stride) ? src[i0 - stride] : 0.f);
        float a1 = src[i1] + ((i1 >= stride) ? src[i1 - stride] : 0.f);
        dst[i0] = (i0 >= stride) ? a0 : src[i0];
        dst[i1] = (i1 >= stride) ? a1 : src[i1];
        __syncthreads();
        float* tmp = src; src = dst; dst = tmp;
    }
    float* s_cum = src;   // final scan result

    // --- systematic resampling: idx = searchsorted(cum, (i+u)/P), left ----
    const float u = resample_u[0];
    #pragma unroll
    for (int k = 0; k < 2; k++) {
        int i = (k == 0) ? i0 : i1;
        float pos = __fdiv_rn(__fadd_rn((float)i, u), (float)NP);
        int lo = 0, hi = NP;
        while (lo < hi) {
            int mid = (lo + hi) >> 1;
            if (s_cum[mid] < pos) lo = mid + 1;
            else hi = mid;
        }
        int idx = min(lo, NP - 1);
        out[3 + i*3 + 0] = __fadd_rn(g_pred[idx*3+0], __fmul_rn(noise_after[i*3+0], 0.2f));
        out[3 + i*3 + 1] = __fadd_rn(g_pred[idx*3+1], __fmul_rn(noise_after[i*3+1], 0.2f));
        out[3 + i*3 + 2] = __fadd_rn(g_pred[idx*3+2], __fmul_rn(noise_after[i*3+2], 0.01f));
    }

    if (tid == 0) {
        const float S10 = s_tot[0];
        out[0] = s_tot[1] / S10;
        out[1] = s_tot[2] / S10;
        out[2] = atan2f(s_tot[3] / S10, s_tot[4] / S10);
        out[3 + NP * 3] = s_tot[6] / S1;   // confidence, last element
    }
}

// ---------------------------------------------------------------------------
// Launch
// ---------------------------------------------------------------------------
extern "C" void kernel_launch(void* const* d_in, const int* in_sizes, int n_in,
                              void* d_out, int out_size)
{
    const float* particles    = (const float*)d_in[0];
    const float* log_weights  = (const float*)d_in[1];
    const float* obs_angles   = (const float*)d_in[2];
    const float* obs_dists    = (const float*)d_in[3];
    const float* map_grid     = (const float*)d_in[4];
    const float* sensor_table = (const float*)d_in[5];
    const float* twist        = (const float*)d_in[6];
    const float* motion_noise = (const float*)d_in[7];
    const float* resample_u   = (const float*)d_in[8];
    const float* noise_after  = (const float*)d_in[9];
    float* out = (float*)d_out;

    // Dynamic smem: padded bitmap window + per-ray values + partials
    const int smemA = WIN_U32 * 4 + PPB * 128 * 4 + PPB * 4 * 4;   // ~65.5 KB
    cudaFuncSetAttribute(kernA, cudaFuncAttributeMaxDynamicSharedMemorySize, smemA);

    kernSetup<<<1025, 256>>>(map_grid, obs_angles);
    kernA<<<GRID, TPB, smemA>>>(particles, log_weights, obs_angles, obs_dists,
                                sensor_table, twist, motion_noise);
    kernB<<<1, 1024>>>(noise_after, resample_u, out);
}

// round 8
// speedup vs baseline: 1.1157x; 1.0213x over previous
#include <cuda_runtime.h>
#include <math.h>

// Problem constants
#define NP     2048     // particles
#define NR     128      // rays
#define NS     256      // ray steps
#define MAPW   1024
#define MAPH   1024
#define ND     256      // sensor table dim
#define OCC_THRESH 0.97f

// Map window that can ever be sampled (particles ~N(512,20^2) +-3.6 sigma,
// rays reach <=256.5):  y in [176, 848), x in [160, 864).
#define WINY0   176
#define WROWS   672
#define WINXW0  5            // first x bitmap word (x = 160)
#define WWORDS  22           // x words per row (covers x in [160,864))
#define WT      (WROWS * WWORDS)      // 14784 compact window words
#define WPAD    23           // padded smem row stride (odd -> conflict-free)
#define WIN_U32 (WROWS * WPAD)

#define PPB 7                // particles per block
#define TPB (PPB * 128)      // 896 threads
#define GRID ((NP + PPB - 1) / PPB)   // 293 -> 2 blocks/SM, 56 warps/SM

// Scratch (no cudaMalloc allowed)
__device__ float    g_pred[NP * 3];     // predicted particles
__device__ float    g_trig[NP * 2];     // sin(th), cos(th)
__device__ float    g_logl[NP];         // per-particle log likelihood
__device__ float    g_logits[NP];       // log_weights + log_l
__device__ float    g_cum[NP];          // normalized-weight cumsum
__device__ __align__(16) unsigned g_win[WT];   // compact window occupancy bits
__device__ int      g_perm[NR];         // rays sorted by angle

// ---------------------------------------------------------------------------
// Setup: blocks 0..461 build the COMPACT WINDOW bitmap (8 threads per word,
// float4 loads, ballot-OR packing); block 462 rank-sorts the ray angles.
// ---------------------------------------------------------------------------
__global__ __launch_bounds__(256) void kernSetup(
    const float* __restrict__ map_grid,
    const float* __restrict__ obs_angles)
{
    if (blockIdx.x < (WT * 8) / 256) {                    // 462 blocks
        const int gid = blockIdx.x * 256 + threadIdx.x;   // 0 .. 118271
        const int w   = gid >> 3;                         // window word
        const int sub = gid & 7;                          // float4 within word
        const int row = w / WWORDS;
        const int cw  = w - row * WWORDS;
        const int cell = (row + WINY0) * MAPW + (WINXW0 * 32) + cw * 32 + sub * 4;
        const float4 v = __ldg((const float4*)(map_grid + cell));
        unsigned b = (v.x > OCC_THRESH ? 1u : 0u)
                   | (v.y > OCC_THRESH ? 2u : 0u)
                   | (v.z > OCC_THRESH ? 4u : 0u)
                   | (v.w > OCC_THRESH ? 8u : 0u);
        const int lane = threadIdx.x & 31;
        const int grp  = lane >> 3;                       // 8-lane group = 1 word
        const unsigned gmask = 0xFFu << (grp * 8);
        unsigned word = __reduce_or_sync(gmask, b << (sub * 4));
        if (sub == 0) g_win[w] = word;
    } else {
        __shared__ float s_a[NR];
        const int i = threadIdx.x;
        if (i < NR) s_a[i] = obs_angles[i];
        __syncthreads();
        if (i < NR) {
            const float a = s_a[i];
            int rank = 0;
            #pragma unroll 8
            for (int j = 0; j < NR; j++) {
                float b = s_a[j];
                rank += (b < a) || (b == a && j < i);
            }
            g_perm[rank] = i;
        }
    }
}

// ---------------------------------------------------------------------------
// Kernel A (R5 layout): 7 particles/block, 128 threads/particle; each warp
// serially processes its 32 (angle-sorted) rays, 32 steps/iteration with
// ballot first-hit.  Compact window bitmap cached in padded smem.  Per-ray
// values stored by ORIGINAL ray index; reduction in exact R1 order.
// ---------------------------------------------------------------------------
__global__ __launch_bounds__(TPB, 2) void kernA(
    const float* __restrict__ particles,
    const float* __restrict__ log_weights,
    const float* __restrict__ obs_angles,
    const float* __restrict__ obs_dists,
    const float* __restrict__ map_grid,
    const float* __restrict__ sensor_table,
    const float* __restrict__ twist,
    const float* __restrict__ motion_noise)
{
    extern __shared__ unsigned smw[];
    unsigned* sm_bm  = smw;                               // WROWS*WPAD u32
    float*    s_val  = (float*)(smw + WIN_U32);           // PPB*128 floats
    float*    s_part = s_val + PPB * 128;                 // PPB*4 floats

    const int tid = threadIdx.x;

    // ---- copy compact window bitmap into padded smem rows (coalesced) ----
    for (int i = tid; i < WT; i += TPB) {
        int row = i / WWORDS;
        int j   = i - row * WWORDS;
        sm_bm[row * WPAD + j] = __ldg(&g_win[i]);
    }

    const int pi   = tid >> 7;        // particle within block
    const int r    = tid & 127;       // sorted-rank ray slot
    const int lane = tid & 31;
    const int p    = blockIdx.x * PPB + pi;
    const bool active = (p < NP);     // uniform per warp

    float x = 0.f, y = 0.f, th = 0.f, c = 0.f, s = 0.f;
    int ray = 0;
    bool my_inw = false;
    if (active) {
        ray = g_perm[r];
        // Motion update (mul then add, no FMA contraction)
        x  = __fadd_rn(__fadd_rn(particles[p*3+0], twist[0]),
                       __fmul_rn(motion_noise[p*3+0], 0.5f));
        y  = __fadd_rn(__fadd_rn(particles[p*3+1], twist[1]),
                       __fmul_rn(motion_noise[p*3+1], 0.5f));
        th = __fadd_rn(__fadd_rn(particles[p*3+2], twist[2]),
                       __fmul_rn(motion_noise[p*3+2], 0.02f));
        if (r < 3) g_pred[p*3 + r] = (r == 0) ? x : ((r == 1) ? y : th);
        if (r == 3) g_trig[p*2 + 0] = sinf(th);
        if (r == 4) g_trig[p*2 + 1] = cosf(th);

        const float ang = __fadd_rn(th, obs_angles[ray]);
        c = cosf(ang);
        s = sinf(ang);

        // In-window test for this ray's whole segment (t in [1,256], convex)
        float ex0 = __fadd_rn(x, c), ex1 = __fadd_rn(x, __fmul_rn(256.f, c));
        float ey0 = __fadd_rn(y, s), ey1 = __fadd_rn(y, __fmul_rn(256.f, s));
        float xmn = fminf(ex0, ex1), xmx = fmaxf(ex0, ex1);
        float ymn = fminf(ey0, ey1), ymx = fmaxf(ey0, ey1);
        my_inw = (xmn >= 162.f) && (xmx < 862.f) &&
                 (ymn >= (float)(WINY0 + 2)) && (ymx < (float)(WINY0 + WROWS - 2));
    }

    __syncthreads();   // smem bitmap ready

    int my_ebin = 255;   // no-hit: dist=256 -> clip(int(256),0,255)=255
    if (active) {
        const unsigned inw_mask = __ballot_sync(0xffffffffu, my_inw);
        const float lanef = (float)(lane + 1);

        #pragma unroll 1
        for (int rr = 0; rr < 32; rr++) {
            const float rc = __shfl_sync(0xffffffffu, c, rr);
            const float rs = __shfl_sync(0xffffffffu, s, rr);
            int ebin = 255;
            if ((inw_mask >> rr) & 1u) {
                // Fast path: padded smem window, no clamping needed.
                float tf = lanef;
                #pragma unroll 1
                for (int it = 0; it < 8; it++) {
                    float px = __fadd_rn(x, __fmul_rn(tf, rc));
                    float py = __fadd_rn(y, __fmul_rn(tf, rs));
                    int ix = __float2int_rz(px);
                    int iy = __float2int_rz(py);
                    unsigned w = sm_bm[(iy - WINY0) * WPAD + ((ix >> 5) - WINXW0)];
                    unsigned m = __ballot_sync(0xffffffffu, (w >> (ix & 31)) & 1u);
                    if (m) { ebin = min(it * 32 + __ffs(m), 255); break; }
                    tf = __fadd_rn(tf, 32.0f);
                }
            } else {
                // Fallback: read the map directly with full clamping (same
                // boolean as the bitmap bit; outliers only, never taken here).
                float tf = lanef;
                #pragma unroll 1
                for (int it = 0; it < 8; it++) {
                    float px = __fadd_rn(x, __fmul_rn(tf, rc));
                    float py = __fadd_rn(y, __fmul_rn(tf, rs));
                    int ix = min(max(__float2int_rz(px), 0), MAPW - 1);
                    int iy = min(max(__float2int_rz(py), 0), MAPH - 1);
                    bool occ = __ldg(&map_grid[iy * MAPW + ix]) > OCC_THRESH;
                    unsigned m = __ballot_sync(0xffffffffu, occ);
                    if (m) { ebin = min(it * 32 + __ffs(m), 255); break; }
                    tf = __fadd_rn(tf, 32.0f);
                }
            }
            my_ebin = (lane == rr) ? ebin : my_ebin;
        }

        // bin_w = 1.0 exactly: o_bin = clip(int(obs_dist),0,255)
        int ob = min(max(__float2int_rz(obs_dists[ray]), 0), ND - 1);
        float val = __ldg(&sensor_table[my_ebin * ND + ob]);
        s_val[pi * 128 + ray] = val;          // store by ORIGINAL ray index
    }
    __syncthreads();

    // Reduce in the exact round-1 order: thread slot r <- ray r.
    if (active) {
        float v = s_val[pi * 128 + r];
        #pragma unroll
        for (int o = 16; o > 0; o >>= 1)
            v += __shfl_down_sync(0xffffffffu, v, o);
        if ((r & 31) == 0) s_part[pi * 4 + (r >> 5)] = v;
    }
    __syncthreads();
    if (active && r == 0) {
        float ll = ((s_part[pi*4+0] + s_part[pi*4+1]) + s_part[pi*4+2]) + s_part[pi*4+3];
        g_logl[p] = ll;
        g_logits[p] = __fadd_rn(log_weights[p], __fmul_rn(1.0f, ll));
    }
}

// ---------------------------------------------------------------------------
// Kernel B1: single block, 1024 threads.  Max + 7 FUSED reductions (validated
// bit-exact), ping-pong Kogge-Stone scan (validated bit-exact).  Writes g_cum
// and the estimate/confidence outputs.
// ---------------------------------------------------------------------------
__global__ __launch_bounds__(1024) void kernB1(float* __restrict__ out)
{
    __shared__ float s_buf0[NP];
    __shared__ float s_buf1[NP];
    __shared__ float s_red[7 * 32];
    __shared__ float s_tot[8];

    const int tid  = threadIdx.x;
    const int lane = tid & 31;
    const int wrp  = tid >> 5;
    const int i0 = tid, i1 = tid + 1024;

    // --- max of logits (same shfl_down tree as R1) ---
    float l0 = g_logits[i0];
    float l1 = g_logits[i1];
    {
        float v = fmaxf(l0, l1);
        #pragma unroll
        for (int o = 16; o > 0; o >>= 1)
            v = fmaxf(v, __shfl_down_sync(0xffffffffu, v, o));
        if (lane == 0) s_red[wrp] = v;
        __syncthreads();
        if (wrp == 0) {
            float m2 = s_red[lane];
            #pragma unroll
            for (int o = 16; o > 0; o >>= 1)
                m2 = fmaxf(m2, __shfl_down_sync(0xffffffffu, m2, o));
            if (lane == 0) s_tot[7] = m2;
        }
        __syncthreads();
    }
    const float mx   = s_tot[7];
    const float mx10 = __fmul_rn(mx, 10.0f);

    // --- exp terms + 7 fused weighted partial sums ---
    float acc[7] = {0.f, 0.f, 0.f, 0.f, 0.f, 0.f, 0.f};
    #pragma unroll
    for (int k = 0; k < 2; k++) {
        int i = (k == 0) ? i0 : i1;
        float l = (k == 0) ? l0 : l1;
        float e10 = expf(__fsub_rn(__fmul_rn(l, 10.0f), mx10));
        float e1  = expf(__fsub_rn(l, mx));
        float px = g_pred[i*3+0];
        float py = g_pred[i*3+1];
        acc[0] += e10;                  // S10
        acc[1] += e10 * px;             // Sx
        acc[2] += e10 * py;             // Sy
        acc[3] += e10 * g_trig[i*2+0];  // Ssin (same bits as e10*sinf(th))
        acc[4] += e10 * g_trig[i*2+1];  // Scos
        acc[5] += e1;                   // S1
        acc[6] += e1 * g_logl[i];       // Sconf
        s_buf0[i] = e1;
    }
    #pragma unroll
    for (int q = 0; q < 7; q++) {
        float v = acc[q];
        #pragma unroll
        for (int o = 16; o > 0; o >>= 1)
            v += __shfl_down_sync(0xffffffffu, v, o);
        if (lane == 0) s_red[q * 32 + wrp] = v;
    }
    __syncthreads();
    if (wrp == 0) {
        #pragma unroll
        for (int q = 0; q < 7; q++) {
            float v = s_red[q * 32 + lane];
            #pragma unroll
            for (int o = 16; o > 0; o >>= 1)
                v += __shfl_down_sync(0xffffffffu, v, o);
            if (lane == 0) s_tot[q] = v;
        }
    }
    __syncthreads();
    const float S1 = s_tot[5];

    // --- normalize weights ---
    s_buf0[i0] = s_buf0[i0] / S1;
    s_buf0[i1] = s_buf0[i1] / S1;
    __syncthreads();

    // --- Kogge-Stone inclusive scan, ping-pong (bit-exact, 1 barrier/round) ---
    float* src = s_buf0;
    float* dst = s_buf1;
    for (int stride = 1; stride < NP; stride <<= 1) {
        float a0 = src[i0] + ((i0 >= stride) ? src[i0 - stride] : 0.f);
        float a1 = src[i1] + ((i1 >= stride) ? src[i1 - stride] : 0.f);
        dst[i0] = (i0 >= stride) ? a0 : src[i0];
        dst[i1] = (i1 >= stride) ? a1 : src[i1];
        __syncthreads();
        float* tmp = src; src = dst; dst = tmp;
    }
    g_cum[i0] = src[i0];
    g_cum[i1] = src[i1];

    if (tid == 0) {
        const float S10 = s_tot[0];
        out[0] = s_tot[1] / S10;
        out[1] = s_tot[2] / S10;
        out[2] = atan2f(s_tot[3] / S10, s_tot[4] / S10);
        out[3 + NP * 3] = s_tot[6] / S1;   // confidence, last element
    }
}

// ---------------------------------------------------------------------------
// Kernel B2 (R5 verbatim): 8 blocks x 256.  Systematic resampling + gather +
// noise.  cum staged through smem; arithmetic identical to round 1.
// ---------------------------------------------------------------------------
__global__ __launch_bounds__(256) void kernB2(
    const float* __restrict__ noise_after,
    const float* __restrict__ resample_u,
    float* __restrict__ out)
{
    __shared__ float s_cum[NP];
    const int tid = threadIdx.x;
    #pragma unroll
    for (int k = 0; k < NP / 256; k++)
        s_cum[k * 256 + tid] = g_cum[k * 256 + tid];
    __syncthreads();

    const int i = blockIdx.x * 256 + tid;
    const float u = resample_u[0];
    float pos = __fdiv_rn(__fadd_rn((float)i, u), (float)NP);
    int lo = 0, hi = NP;
    while (lo < hi) {
        int mid = (lo + hi) >> 1;
        if (s_cum[mid] < pos) lo = mid + 1;
        else hi = mid;
    }
    int idx = min(lo, NP - 1);
    // new_p = p[idx] + noise_after * SIGMA_NOISE, SIGMA_NOISE=(0.2,0.2,0.01)
    out[3 + i*3 + 0] = __fadd_rn(g_pred[idx*3+0], __fmul_rn(noise_after[i*3+0], 0.2f));
    out[3 + i*3 + 1] = __fadd_rn(g_pred[idx*3+1], __fmul_rn(noise_after[i*3+1], 0.2f));
    out[3 + i*3 + 2] = __fadd_rn(g_pred[idx*3+2], __fmul_rn(noise_after[i*3+2], 0.01f));
}

// ---------------------------------------------------------------------------
// Launch
// ---------------------------------------------------------------------------
extern "C" void kernel_launch(void* const* d_in, const int* in_sizes, int n_in,
                              void* d_out, int out_size)
{
    const float* particles    = (const float*)d_in[0];
    const float* log_weights  = (const float*)d_in[1];
    const float* obs_angles   = (const float*)d_in[2];
    const float* obs_dists    = (const float*)d_in[3];
    const float* map_grid     = (const float*)d_in[4];
    const float* sensor_table = (const float*)d_in[5];
    const float* twist        = (const float*)d_in[6];
    const float* motion_noise = (const float*)d_in[7];
    const float* resample_u   = (const float*)d_in[8];
    const float* noise_after  = (const float*)d_in[9];
    float* out = (float*)d_out;

    // Dynamic smem: padded bitmap window + per-ray values + partials
    const int smemA = WIN_U32 * 4 + PPB * 128 * 4 + PPB * 4 * 4;   // ~65.5 KB
    cudaFuncSetAttribute(kernA, cudaFuncAttributeMaxDynamicSharedMemorySize, smemA);

    kernSetup<<<(WT * 8) / 256 + 1, 256>>>(map_grid, obs_angles);
    kernA<<<GRID, TPB, smemA>>>(particles, log_weights, obs_angles, obs_dists,
                                map_grid, sensor_table, twist, motion_noise);
    kernB1<<<1, 1024>>>(out);
    kernB2<<<NP / 256, 256>>>(noise_after, resample_u, out);
}

// round 9
// speedup vs baseline: 1.1234x; 1.0069x over previous
#include <cuda_runtime.h>
#include <math.h>

// Problem constants
#define NP     2048     // particles
#define NR     128      // rays
#define NS     256      // ray steps
#define MAPW   1024
#define MAPH   1024
#define ND     256      // sensor table dim
#define OCC_THRESH 0.97f

// Map window that can ever be sampled (particles ~N(512,20^2) +-3.6 sigma,
// rays reach <=256.5):  y in [176, 848), x in [160, 864).
#define WINY0   176
#define WROWS   672
#define WINXW0  5            // first x bitmap word (x = 160)
#define WWORDS  22           // x words per row (covers x in [160,864))
#define WT      (WROWS * WWORDS)      // 14784 compact window words
#define WPAD    23           // padded smem row stride (odd -> conflict-free)
#define WIN_U32 (WROWS * WPAD)

#define PPB 7                // particles per block
#define TPB (PPB * 128)      // 896 threads
#define GRID ((NP + PPB - 1) / PPB)   // 293 -> 2 blocks/SM, 56 warps/SM

// Scratch (no cudaMalloc allowed)
__device__ float    g_pred[NP * 3];     // predicted particles
__device__ float    g_trig[NP * 2];     // sin(th), cos(th)
__device__ float    g_logl[NP];         // per-particle log likelihood
__device__ float    g_logits[NP];       // log_weights + log_l
__device__ float    g_cum[NP];          // normalized-weight cumsum
__device__ __align__(16) unsigned g_win[WT];   // compact window occupancy bits
__device__ int      g_perm[NR];         // rays sorted by angle

// ---------------------------------------------------------------------------
// Setup: blocks 0..461 build the COMPACT WINDOW bitmap (8 threads per word,
// float4 loads, ballot-OR packing); block 462 rank-sorts the ray angles.
// ---------------------------------------------------------------------------
__global__ __launch_bounds__(256) void kernSetup(
    const float* __restrict__ map_grid,
    const float* __restrict__ obs_angles)
{
    if (blockIdx.x < (WT * 8) / 256) {                    // 462 blocks
        const int gid = blockIdx.x * 256 + threadIdx.x;   // 0 .. 118271
        const int w   = gid >> 3;                         // window word
        const int sub = gid & 7;                          // float4 within word
        const int row = w / WWORDS;
        const int cw  = w - row * WWORDS;
        const int cell = (row + WINY0) * MAPW + (WINXW0 * 32) + cw * 32 + sub * 4;
        const float4 v = __ldg((const float4*)(map_grid + cell));
        unsigned b = (v.x > OCC_THRESH ? 1u : 0u)
                   | (v.y > OCC_THRESH ? 2u : 0u)
                   | (v.z > OCC_THRESH ? 4u : 0u)
                   | (v.w > OCC_THRESH ? 8u : 0u);
        const int lane = threadIdx.x & 31;
        const int grp  = lane >> 3;                       // 8-lane group = 1 word
        const unsigned gmask = 0xFFu << (grp * 8);
        unsigned word = __reduce_or_sync(gmask, b << (sub * 4));
        if (sub == 0) g_win[w] = word;
    } else {
        __shared__ float s_a[NR];
        const int i = threadIdx.x;
        if (i < NR) s_a[i] = obs_angles[i];
        __syncthreads();
        if (i < NR) {
            const float a = s_a[i];
            int rank = 0;
            #pragma unroll 8
            for (int j = 0; j < NR; j++) {
                float b = s_a[j];
                rank += (b < a) || (b == a && j < i);
            }
            g_perm[rank] = i;
        }
    }
}

// ---------------------------------------------------------------------------
// Kernel A (R5 layout): 7 particles/block, 128 threads/particle; each warp
// serially processes its 32 (angle-sorted) rays, 32 steps/iteration with
// ballot first-hit.  Compact window bitmap cached in padded smem.  Per-ray
// values stored by ORIGINAL ray index; reduction in exact R1 order.
// ---------------------------------------------------------------------------
__global__ __launch_bounds__(TPB, 2) void kernA(
    const float* __restrict__ particles,
    const float* __restrict__ log_weights,
    const float* __restrict__ obs_angles,
    const float* __restrict__ obs_dists,
    const float* __restrict__ map_grid,
    const float* __restrict__ sensor_table,
    const float* __restrict__ twist,
    const float* __restrict__ motion_noise)
{
    extern __shared__ unsigned smw[];
    unsigned* sm_bm  = smw;                               // WROWS*WPAD u32
    float*    s_val  = (float*)(smw + WIN_U32);           // PPB*128 floats
    float*    s_part = s_val + PPB * 128;                 // PPB*4 floats

    const int tid = threadIdx.x;

    // ---- copy compact window bitmap into padded smem rows (coalesced) ----
    for (int i = tid; i < WT; i += TPB) {
        int row = i / WWORDS;
        int j   = i - row * WWORDS;
        sm_bm[row * WPAD + j] = __ldg(&g_win[i]);
    }

    const int pi   = tid >> 7;        // particle within block
    const int r    = tid & 127;       // sorted-rank ray slot
    const int lane = tid & 31;
    const int p    = blockIdx.x * PPB + pi;
    const bool active = (p < NP);     // uniform per warp

    float x = 0.f, y = 0.f, th = 0.f, c = 0.f, s = 0.f;
    int ray = 0;
    bool my_inw = false;
    if (active) {
        ray = g_perm[r];
        // Motion update (mul then add, no FMA contraction)
        x  = __fadd_rn(__fadd_rn(particles[p*3+0], twist[0]),
                       __fmul_rn(motion_noise[p*3+0], 0.5f));
        y  = __fadd_rn(__fadd_rn(particles[p*3+1], twist[1]),
                       __fmul_rn(motion_noise[p*3+1], 0.5f));
        th = __fadd_rn(__fadd_rn(particles[p*3+2], twist[2]),
                       __fmul_rn(motion_noise[p*3+2], 0.02f));
        if (r < 3) g_pred[p*3 + r] = (r == 0) ? x : ((r == 1) ? y : th);
        if (r == 3) g_trig[p*2 + 0] = sinf(th);
        if (r == 4) g_trig[p*2 + 1] = cosf(th);

        const float ang = __fadd_rn(th, obs_angles[ray]);
        c = cosf(ang);
        s = sinf(ang);

        // In-window test for this ray's whole segment (t in [1,256], convex)
        float ex0 = __fadd_rn(x, c), ex1 = __fadd_rn(x, __fmul_rn(256.f, c));
        float ey0 = __fadd_rn(y, s), ey1 = __fadd_rn(y, __fmul_rn(256.f, s));
        float xmn = fminf(ex0, ex1), xmx = fmaxf(ex0, ex1);
        float ymn = fminf(ey0, ey1), ymx = fmaxf(ey0, ey1);
        my_inw = (xmn >= 162.f) && (xmx < 862.f) &&
                 (ymn >= (float)(WINY0 + 2)) && (ymx < (float)(WINY0 + WROWS - 2));
    }

    __syncthreads();   // smem bitmap ready

    int my_ebin = 255;   // no-hit: dist=256 -> clip(int(256),0,255)=255
    if (active) {
        const unsigned inw_mask = __ballot_sync(0xffffffffu, my_inw);
        const float lanef = (float)(lane + 1);

        #pragma unroll 1
        for (int rr = 0; rr < 32; rr++) {
            const float rc = __shfl_sync(0xffffffffu, c, rr);
            const float rs = __shfl_sync(0xffffffffu, s, rr);
            int ebin = 255;
            if ((inw_mask >> rr) & 1u) {
                // Fast path: padded smem window, no clamping needed.
                float tf = lanef;
                #pragma unroll 1
                for (int it = 0; it < 8; it++) {
                    float px = __fadd_rn(x, __fmul_rn(tf, rc));
                    float py = __fadd_rn(y, __fmul_rn(tf, rs));
                    int ix = __float2int_rz(px);
                    int iy = __float2int_rz(py);
                    unsigned w = sm_bm[(iy - WINY0) * WPAD + ((ix >> 5) - WINXW0)];
                    unsigned m = __ballot_sync(0xffffffffu, (w >> (ix & 31)) & 1u);
                    if (m) { ebin = min(it * 32 + __ffs(m), 255); break; }
                    tf = __fadd_rn(tf, 32.0f);
                }
            } else {
                // Fallback: read the map directly with full clamping (same
                // boolean as the bitmap bit; outliers only, never taken here).
                float tf = lanef;
                #pragma unroll 1
                for (int it = 0; it < 8; it++) {
                    float px = __fadd_rn(x, __fmul_rn(tf, rc));
                    float py = __fadd_rn(y, __fmul_rn(tf, rs));
                    int ix = min(max(__float2int_rz(px), 0), MAPW - 1);
                    int iy = min(max(__float2int_rz(py), 0), MAPH - 1);
                    bool occ = __ldg(&map_grid[iy * MAPW + ix]) > OCC_THRESH;
                    unsigned m = __ballot_sync(0xffffffffu, occ);
                    if (m) { ebin = min(it * 32 + __ffs(m), 255); break; }
                    tf = __fadd_rn(tf, 32.0f);
                }
            }
            my_ebin = (lane == rr) ? ebin : my_ebin;
        }

        // bin_w = 1.0 exactly: o_bin = clip(int(obs_dist),0,255)
        int ob = min(max(__float2int_rz(obs_dists[ray]), 0), ND - 1);
        float val = __ldg(&sensor_table[my_ebin * ND + ob]);
        s_val[pi * 128 + ray] = val;          // store by ORIGINAL ray index
    }
    __syncthreads();

    // Reduce in the exact round-1 order: thread slot r <- ray r.
    if (active) {
        float v = s_val[pi * 128 + r];
        #pragma unroll
        for (int o = 16; o > 0; o >>= 1)
            v += __shfl_down_sync(0xffffffffu, v, o);
        if ((r & 31) == 0) s_part[pi * 4 + (r >> 5)] = v;
    }
    __syncthreads();
    if (active && r == 0) {
        float ll = ((s_part[pi*4+0] + s_part[pi*4+1]) + s_part[pi*4+2]) + s_part[pi*4+3];
        g_logl[p] = ll;
        g_logits[p] = __fadd_rn(log_weights[p], __fmul_rn(1.0f, ll));
    }
}

// ---------------------------------------------------------------------------
// Kernel B1: single block, 1024 threads.  Max + 7 FUSED reductions (validated
// bit-exact), ping-pong Kogge-Stone scan (validated bit-exact).  Writes g_cum
// and the estimate/confidence outputs.
// ---------------------------------------------------------------------------
__global__ __launch_bounds__(1024) void kernB1(float* __restrict__ out)
{
    __shared__ float s_buf0[NP];
    __shared__ float s_buf1[NP];
    __shared__ float s_red[7 * 32];
    __shared__ float s_tot[8];

    const int tid  = threadIdx.x;
    const int lane = tid & 31;
    const int wrp  = tid >> 5;
    const int i0 = tid, i1 = tid + 1024;

    // --- max of logits (same shfl_down tree as R1) ---
    float l0 = g_logits[i0];
    float l1 = g_logits[i1];
    {
        float v = fmaxf(l0, l1);
        #pragma unroll
        for (int o = 16; o > 0; o >>= 1)
            v = fmaxf(v, __shfl_down_sync(0xffffffffu, v, o));
        if (lane == 0) s_red[wrp] = v;
        __syncthreads();
        if (wrp == 0) {
            float m2 = s_red[lane];
            #pragma unroll
            for (int o = 16; o > 0; o >>= 1)
                m2 = fmaxf(m2, __shfl_down_sync(0xffffffffu, m2, o));
            if (lane == 0) s_tot[7] = m2;
        }
        __syncthreads();
    }
    const float mx   = s_tot[7];
    const float mx10 = __fmul_rn(mx, 10.0f);

    // --- exp terms + 7 fused weighted partial sums ---
    float acc[7] = {0.f, 0.f, 0.f, 0.f, 0.f, 0.f, 0.f};
    #pragma unroll
    for (int k = 0; k < 2; k++) {
        int i = (k == 0) ? i0 : i1;
        float l = (k == 0) ? l0 : l1;
        float e10 = expf(__fsub_rn(__fmul_rn(l, 10.0f), mx10));
        float e1  = expf(__fsub_rn(l, mx));
        float px = g_pred[i*3+0];
        float py = g_pred[i*3+1];
        acc[0] += e10;                  // S10
        acc[1] += e10 * px;             // Sx
        acc[2] += e10 * py;             // Sy
        acc[3] += e10 * g_trig[i*2+0];  // Ssin (same bits as e10*sinf(th))
        acc[4] += e10 * g_trig[i*2+1];  // Scos
        acc[5] += e1;                   // S1
        acc[6] += e1 * g_logl[i];       // Sconf
        s_buf0[i] = e1;
    }
    #pragma unroll
    for (int q = 0; q < 7; q++) {
        float v = acc[q];
        #pragma unroll
        for (int o = 16; o > 0; o >>= 1)
            v += __shfl_down_sync(0xffffffffu, v, o);
        if (lane == 0) s_red[q * 32 + wrp] = v;
    }
    __syncthreads();
    if (wrp == 0) {
        #pragma unroll
        for (int q = 0; q < 7; q++) {
            float v = s_red[q * 32 + lane];
            #pragma unroll
            for (int o = 16; o > 0; o >>= 1)
                v += __shfl_down_sync(0xffffffffu, v, o);
            if (lane == 0) s_tot[q] = v;
        }
    }
    __syncthreads();
    const float S1 = s_tot[5];

    // --- normalize weights ---
    s_buf0[i0] = s_buf0[i0] / S1;
    s_buf0[i1] = s_buf0[i1] / S1;
    __syncthreads();

    // --- Kogge-Stone inclusive scan, ping-pong (bit-exact, 1 barrier/round) ---
    float* src = s_buf0;
    float* dst = s_buf1;
    for (int stride = 1; stride < NP; stride <<= 1) {
        float a0 = src[i0] + ((i0 >= stride) ? src[i0 - stride] : 0.f);
        float a1 = src[i1] + ((i1 >= stride) ? src[i1 - stride] : 0.f);
        dst[i0] = (i0 >= stride) ? a0 : src[i0];
        dst[i1] = (i1 >= stride) ? a1 : src[i1];
        __syncthreads();
        float* tmp = src; src = dst; dst = tmp;
    }
    g_cum[i0] = src[i0];
    g_cum[i1] = src[i1];

    if (tid == 0) {
        const float S10 = s_tot[0];
        out[0] = s_tot[1] / S10;
        out[1] = s_tot[2] / S10;
        out[2] = atan2f(s_tot[3] / S10, s_tot[4] / S10);
        out[3 + NP * 3] = s_tot[6] / S1;   // confidence, last element
    }
}

// ---------------------------------------------------------------------------
// Kernel B2 (R5 verbatim): 8 blocks x 256.  Systematic resampling + gather +
// noise.  cum staged through smem; arithmetic identical to round 1.
// ---------------------------------------------------------------------------
__global__ __launch_bounds__(256) void kernB2(
    const float* __restrict__ noise_after,
    const float* __restrict__ resample_u,
    float* __restrict__ out)
{
    __shared__ float s_cum[NP];
    const int tid = threadIdx.x;
    #pragma unroll
    for (int k = 0; k < NP / 256; k++)
        s_cum[k * 256 + tid] = g_cum[k * 256 + tid];
    __syncthreads();

    const int i = blockIdx.x * 256 + tid;
    const float u = resample_u[0];
    float pos = __fdiv_rn(__fadd_rn((float)i, u), (float)NP);
    int lo = 0, hi = NP;
    while (lo < hi) {
        int mid = (lo + hi) >> 1;
        if (s_cum[mid] < pos) lo = mid + 1;
        else hi = mid;
    }
    int idx = min(lo, NP - 1);
    // new_p = p[idx] + noise_after * SIGMA_NOISE, SIGMA_NOISE=(0.2,0.2,0.01)
    out[3 + i*3 + 0] = __fadd_rn(g_pred[idx*3+0], __fmul_rn(noise_after[i*3+0], 0.2f));
    out[3 + i*3 + 1] = __fadd_rn(g_pred[idx*3+1], __fmul_rn(noise_after[i*3+1], 0.2f));
    out[3 + i*3 + 2] = __fadd_rn(g_pred[idx*3+2], __fmul_rn(noise_after[i*3+2], 0.01f));
}

// ---------------------------------------------------------------------------
// Launch
// ---------------------------------------------------------------------------
extern "C" void kernel_launch(void* const* d_in, const int* in_sizes, int n_in,
                              void* d_out, int out_size)
{
    const float* particles    = (const float*)d_in[0];
    const float* log_weights  = (const float*)d_in[1];
    const float* obs_angles   = (const float*)d_in[2];
    const float* obs_dists    = (const float*)d_in[3];
    const float* map_grid     = (const float*)d_in[4];
    const float* sensor_table = (const float*)d_in[5];
    const float* twist        = (const float*)d_in[6];
    const float* motion_noise = (const float*)d_in[7];
    const float* resample_u   = (const float*)d_in[8];
    const float* noise_after  = (const float*)d_in[9];
    float* out = (float*)d_out;

    // Dynamic smem: padded bitmap window + per-ray values + partials
    const int smemA = WIN_U32 * 4 + PPB * 128 * 4 + PPB * 4 * 4;   // ~65.5 KB
    cudaFuncSetAttribute(kernA, cudaFuncAttributeMaxDynamicSharedMemorySize, smemA);

    kernSetup<<<(WT * 8) / 256 + 1, 256>>>(map_grid, obs_angles);
    kernA<<<GRID, TPB, smemA>>>(particles, log_weights, obs_angles, obs_dists,
                                map_grid, sensor_table, twist, motion_noise);
    kernB1<<<1, 1024>>>(out);
    kernB2<<<NP / 256, 256>>>(noise_after, resample_u, out);
}